// round 13
// baseline (speedup 1.0000x reference)
#include <cuda_runtime.h>
#include <cuda_fp16.h>
#include <cstdint>

#define N_ROWS 4096
#define VOCAB  50000
#define DIM    64

#define BM 128
#define BN 128
#define TPB   391                 // column tiles per row-block
#define MB    32                  // row blocks
#define CHUNK 4                   // row blocks per pipeline stage
#define NCH   (MB / CHUNK)        // 8 stages
#define TPCH  (CHUNK * TPB)       // 1564 tiles per stage
#define GRID0 296                 // pass0 CTAs per stage (2/SM alone; fills 3rd slot co-resident)
#define GRID1 296                 // pass1 strip CTAs per stage

#define ROWB 144                  // bytes per smem tile row (72 halves, conflict-free)
#define A_SM_BYTES (BM * ROWB)    // 18432
#define SMEM_TOTAL (3 * A_SM_BYTES)   // A + B double buffer = 55296

#define LOG2E 1.4426950408889634f

// scratch (no allocs allowed -> device globals)
__device__ float  g_sums[N_ROWS];
__device__ float  g_loss;
__device__ int    g_loss_cnt;
__device__ __half g_A16[N_ROWS * DIM];   // pre-scaled by log2e
__device__ __half g_B16[VOCAB * DIM];

__device__ __forceinline__ uint32_t smem_u32(const void* p) {
    uint32_t a;
    asm("{ .reg .u64 t; cvta.to.shared.u64 t, %1; cvt.u32.u64 %0, t; }" : "=r"(a) : "l"(p));
    return a;
}
__device__ __forceinline__ float ex2f(float x) {      // exp(logit): logits log2-domain
    float y;
    asm("ex2.approx.f32 %0, %1;" : "=f"(y) : "f"(x));
    return y;
}
// B-tile column permutation: MMA-space row q = nf*8+lc*2+j holds natural column
// (nf&2)*8 + lc*4 + (nf&1)*2 + j  -> pass-1 stores are full STG.128.
__device__ __forceinline__ int permB(int r) {
    int q = r & 31;
    int nf = q >> 3, lc = (q >> 1) & 3, j = q & 1;
    return (r & ~31) | ((nf & 2) << 3) | (lc << 2) | ((nf & 1) << 1) | j;
}
#define CP_ASYNC16(dst, src, sz) \
    asm volatile("cp.async.cg.shared.global [%0], [%1], 16, %2;" :: "r"(dst), "l"(src), "r"(sz))
#define CP_COMMIT()  asm volatile("cp.async.commit_group;" ::: "memory")
#define CP_WAIT0()   asm volatile("cp.async.wait_group 0;" ::: "memory")
#define LDMATRIX_X4(r0, r1, r2, r3, addr) \
    asm volatile("ldmatrix.sync.aligned.m8n8.x4.shared.b16 {%0,%1,%2,%3}, [%4];" \
                 : "=r"(r0), "=r"(r1), "=r"(r2), "=r"(r3) : "r"(addr))

// init + fp32 -> fp16 convert. A pre-scaled by log2e so exp(logit) == ex2(gemm_out).
__global__ void convert_kernel(const float* __restrict__ A, const float* __restrict__ B) {
    int i = blockIdx.x * blockDim.x + threadIdx.x;
    if (i < N_ROWS) g_sums[i] = 0.f;
    if (i == 0) { g_loss = 0.f; g_loss_cnt = 0; }
    const int nA4 = N_ROWS * DIM / 4;
    const int nB4 = VOCAB * DIM / 4;
    if (i < nA4) {
        float4 v = ((const float4*)A)[i];
        __half2* d = (__half2*)g_A16;
        d[i * 2 + 0] = __floats2half2_rn(v.x * LOG2E, v.y * LOG2E);
        d[i * 2 + 1] = __floats2half2_rn(v.z * LOG2E, v.w * LOG2E);
    }
    int j = i - nA4;
    if (j >= 0 && j < nB4) {
        float4 v = ((const float4*)B)[j];
        __half2* d = (__half2*)g_B16;
        d[j * 2 + 0] = __floats2half2_rn(v.x, v.y);
        d[j * 2 + 1] = __floats2half2_rn(v.z, v.w);
    }
}

// ---- shared strip machinery (R10-proven) ----
struct StripCtx {
    uint32_t sA, sB0, aAddr0, bOff0;
    int tid, lane, wm, wn, mBase, nBase, lr, lc;
};
__device__ __forceinline__ void strip_init(StripCtx& S, char* smem) {
    S.sA = smem_u32(smem);
    S.sB0 = S.sA + A_SM_BYTES;
    S.tid = threadIdx.x;
    S.lane = S.tid & 31;
    int wid = S.tid >> 5;
    S.wm = wid >> 2; S.wn = wid & 3;
    S.mBase = S.wm * 64; S.nBase = S.wn * 32;
    S.lr = S.lane >> 2; S.lc = S.lane & 3;
    S.aAddr0 = S.sA +
        (uint32_t)(S.mBase + ((S.lane >> 3) & 1) * 8 + (S.lane & 7)) * ROWB + (S.lane >> 4) * 16;
    S.bOff0 =
        (uint32_t)(S.nBase + (S.lane >> 4) * 8 + (S.lane & 7)) * ROWB + ((S.lane >> 3) & 1) * 16;
}
__device__ __forceinline__ void prefetchB(const StripCtx& S, int v0, uint32_t dstBase) {
    #pragma unroll
    for (int t = 0; t < 4; t++) {
        int i = S.tid + t * 256;
        int row = i >> 3, c8 = i & 7;
        int v = v0 + permB(row);
        uint32_t dst = dstBase + row * ROWB + c8 * 16;
        const __half* src = g_B16 + (size_t)v * DIM + c8 * 8;
        CP_ASYNC16(dst, src, (v < VOCAB) ? 16 : 0);
    }
    CP_COMMIT();
}
__device__ __forceinline__ void loadA(const StripCtx& S, char* smem, int m0) {
    const uint4* Ag = (const uint4*)(g_A16 + (size_t)m0 * DIM);
    #pragma unroll
    for (int t = 0; t < 4; t++) {
        int i = S.tid + t * 256;
        int row = i >> 3, c8 = i & 7;
        *(uint4*)(smem + row * ROWB + c8 * 16) = Ag[i];
    }
}
// One tile: preload B frags, mf-major slabs (16 MMA + slab epilogue).
template <bool P0>
__device__ __forceinline__ void run_tile(const StripCtx& S, int v0, int m0, int buf,
                                         float* rr, float* __restrict__ out) {
    const uint32_t bAddr0 = S.sB0 + buf * A_SM_BYTES + S.bOff0;
    unsigned bf[4][4][2];
    #pragma unroll
    for (int kk = 0; kk < 4; kk++)
        #pragma unroll
        for (int p = 0; p < 2; p++)
            LDMATRIX_X4(bf[kk][2 * p][0], bf[kk][2 * p][1],
                        bf[kk][2 * p + 1][0], bf[kk][2 * p + 1][1],
                        bAddr0 + p * (16 * ROWB) + kk * 32);
    const bool full = (v0 + BN <= VOCAB);
    #pragma unroll
    for (int mf = 0; mf < 4; mf++) {
        float c[4][4];
        #pragma unroll
        for (int nf = 0; nf < 4; nf++)
            #pragma unroll
            for (int d = 0; d < 4; d++) c[nf][d] = 0.f;
        #pragma unroll
        for (int kk = 0; kk < 4; kk++) {
            unsigned a0, a1, a2, a3;
            LDMATRIX_X4(a0, a1, a2, a3, S.aAddr0 + mf * (16 * ROWB) + kk * 32);
            #pragma unroll
            for (int nf = 0; nf < 4; nf++) {
                asm volatile(
                    "mma.sync.aligned.m16n8k16.row.col.f32.f16.f16.f32 "
                    "{%0,%1,%2,%3}, {%4,%5,%6,%7}, {%8,%9}, {%0,%1,%2,%3};"
                    : "+f"(c[nf][0]), "+f"(c[nf][1]), "+f"(c[nf][2]), "+f"(c[nf][3])
                    : "r"(a0), "r"(a1), "r"(a2), "r"(a3),
                      "r"(bf[kk][nf][0]), "r"(bf[kk][nf][1]));
            }
        }
        if (P0) {
            if (full) {
                #pragma unroll
                for (int h = 0; h < 2; h++) {
                    __half2 hs = __floats2half2_rn(0.f, 0.f);
                    #pragma unroll
                    for (int nf = 0; nf < 4; nf++) {
                        __half2 p = __floats2half2_rn(c[nf][h * 2 + 0], c[nf][h * 2 + 1]);
                        hs = __hadd2(hs, h2exp2(p));
                    }
                    float2 f = __half22float2(hs);
                    rr[mf * 2 + h] += f.x + f.y;
                }
            } else {
                #pragma unroll
                for (int h = 0; h < 2; h++) {
                    float s = 0.f;
                    #pragma unroll
                    for (int nf = 0; nf < 4; nf++) {
                        int col = v0 + S.nBase + (nf >> 1) * 16 + S.lc * 4 + (nf & 1) * 2;
                        float e0 = ex2f(c[nf][h * 2 + 0]);
                        float e1 = ex2f(c[nf][h * 2 + 1]);
                        s += (col     < VOCAB) ? e0 : 0.f;
                        s += (col + 1 < VOCAB) ? e1 : 0.f;
                    }
                    rr[mf * 2 + h] += s;
                }
            }
        } else {
            #pragma unroll
            for (int h = 0; h < 2; h++) {
                const float r = rr[mf * 2 + h];
                const int rl = S.mBase + mf * 16 + h * 8 + S.lr;
                float* op = out + (size_t)(m0 + rl) * VOCAB;
                #pragma unroll
                for (int gg = 0; gg < 2; gg++) {
                    int col = v0 + S.nBase + gg * 16 + S.lc * 4;
                    if (full || col < VOCAB) {   // 50000 % 4 == 0 -> no straddle
                        float4 p;
                        p.x = ex2f(c[2 * gg + 0][h * 2 + 0]) * r;
                        p.y = ex2f(c[2 * gg + 0][h * 2 + 1]) * r;
                        p.z = ex2f(c[2 * gg + 1][h * 2 + 0]) * r;
                        p.w = ex2f(c[2 * gg + 1][h * 2 + 1]) * r;
                        __stcs((float4*)(op + col), p);
                    }
                }
            }
        }
    }
}

// pass0 stage kernel: chunk of 4 row blocks, 296 strip CTAs, sums only.
__global__ void __launch_bounds__(256, 3)
pass0_kernel(int c0) {
    extern __shared__ char smem[];
    StripCtx S; strip_init(S, smem);
    const int b = blockIdx.x;
    const int base = TPCH / GRID0, rem = TPCH % GRID0;   // 5, 84
    const int gBeg = b * base + (b < rem ? b : rem);
    const int gEnd = gBeg + base + (b < rem ? 1 : 0);

    prefetchB(S, (gBeg % TPB) * BN, S.sB0);

    int curM = -1, buf = 0;
    float rr[8];
    #pragma unroll
    for (int k = 0; k < 8; k++) rr[k] = 0.f;

    for (int g = gBeg; g < gEnd; g++) {
        const int m = c0 + g / TPB;
        const int v0 = (g % TPB) * BN;
        if (m != curM) {
            __syncthreads();
            if (curM >= 0) {
                #pragma unroll
                for (int k = 0; k < 8; k++) {
                    float s = rr[k];
                    s += __shfl_xor_sync(0xffffffffu, s, 1);
                    s += __shfl_xor_sync(0xffffffffu, s, 2);
                    if (S.lc == 0)
                        atomicAdd(&g_sums[curM * BM + S.mBase + (k >> 1) * 16 + (k & 1) * 8 + S.lr], s);
                    rr[k] = 0.f;
                }
            }
            loadA(S, smem, m * BM);
            curM = m;
        }
        CP_WAIT0();
        __syncthreads();
        if (g + 1 < gEnd)
            prefetchB(S, ((g + 1) % TPB) * BN, S.sB0 + (buf ^ 1) * A_SM_BYTES);
        run_tile<true>(S, v0, m * BM, buf, rr, nullptr);
        buf ^= 1;
    }
    if (curM >= 0) {
        #pragma unroll
        for (int k = 0; k < 8; k++) {
            float s = rr[k];
            s += __shfl_xor_sync(0xffffffffu, s, 1);
            s += __shfl_xor_sync(0xffffffffu, s, 2);
            if (S.lc == 0)
                atomicAdd(&g_sums[curM * BM + S.mBase + (k >> 1) * 16 + (k & 1) * 8 + S.lr], s);
        }
    }
}

// pass1 stage kernel: same chunk; 296 strip CTAs + 2 loss CTAs. Runs on the
// high-priority stream after the graph edge guarantees pass0(chunk) completed.
__global__ void __launch_bounds__(256, 3)
pass1_kernel(int c0, float* __restrict__ out,
             const int* __restrict__ label_words,
             const float* __restrict__ inp,
             const float* __restrict__ emb,
             long long lossIdx) {
    extern __shared__ char smem[];
    StripCtx S; strip_init(S, smem);
    const int b = blockIdx.x;
    const int tid = threadIdx.x;

    if (b >= GRID1) {                              // loss CTA: 256 rows of this chunk
        bool is64 = true;
        #pragma unroll
        for (int i = 0; i < 64; i++) is64 &= (label_words[2 * i + 1] == 0);
        int r = c0 * BM + (b - GRID1) * 256 + tid;
        int lab = is64 ? label_words[2 * r] : label_words[r];
        const float4* a4 = (const float4*)(inp + (size_t)r * DIM);
        const float4* b4 = (const float4*)(emb + (size_t)lab * DIM);
        float dot = 0.f;
        #pragma unroll
        for (int i = 0; i < DIM / 4; i++) {
            float4 x = a4[i], y = b4[i];
            dot += x.x * y.x + x.y * y.y + x.z * y.z + x.w * y.w;
        }
        float v = logf(__ldcg(&g_sums[r])) - dot;
        float* red = (float*)smem;
        red[tid] = v;
        __syncthreads();
        for (int s = 128; s > 0; s >>= 1) {
            if (tid < s) red[tid] += red[tid + s];
            __syncthreads();
        }
        if (tid == 0) {
            atomicAdd(&g_loss, red[0]);
            __threadfence();
            int c = atomicAdd(&g_loss_cnt, 1);
            if (c == NCH * 2 - 1)
                out[lossIdx] = atomicAdd(&g_loss, 0.f) * (1.0f / (float)N_ROWS);
        }
        return;
    }

    const int base = TPCH / GRID1, rem = TPCH % GRID1;   // 5, 84
    const int gBeg = b * base + (b < rem ? b : rem);
    const int gEnd = gBeg + base + (b < rem ? 1 : 0);

    prefetchB(S, (gBeg % TPB) * BN, S.sB0);

    int curM = -1, buf = 0;
    float rr[8];
    for (int g = gBeg; g < gEnd; g++) {
        const int m = c0 + g / TPB;
        const int v0 = (g % TPB) * BN;
        if (m != curM) {
            __syncthreads();
            loadA(S, smem, m * BM);
            #pragma unroll
            for (int k = 0; k < 8; k++)
                rr[k] = 1.0f / __ldcg(&g_sums[m * BM + S.mBase + (k >> 1) * 16 + (k & 1) * 8 + S.lr]);
            curM = m;
        }
        CP_WAIT0();
        __syncthreads();
        if (g + 1 < gEnd)
            prefetchB(S, ((g + 1) % TPB) * BN, S.sB0 + (buf ^ 1) * A_SM_BYTES);
        run_tile<false>(S, v0, m * BM, buf, rr, out);
        buf ^= 1;
    }
}

extern "C" void kernel_launch(void* const* d_in, const int* in_sizes, int n_in,
                              void* d_out, int out_size) {
    const int*   label = (const int*)d_in[0];      // int32 or int64 (sniffed in-kernel)
    const float* inp   = (const float*)d_in[1];    // [4096, 64]
    const float* emb   = (const float*)d_in[2];    // [50000, 64]
    float* out = (float*)d_out;                    // [4096*50000] probs + [1] loss

    static cudaStream_t sB = nullptr;
    static cudaEvent_t ev[NCH], evJoin;
    if (!sB) {
        int lo = 0, hi = 0;
        cudaDeviceGetStreamPriorityRange(&lo, &hi);
        cudaStreamCreateWithPriority(&sB, cudaStreamNonBlocking, hi);
        for (int i = 0; i < NCH; i++)
            cudaEventCreateWithFlags(&ev[i], cudaEventDisableTiming);
        cudaEventCreateWithFlags(&evJoin, cudaEventDisableTiming);
        cudaFuncSetAttribute(pass0_kernel,
                             cudaFuncAttributeMaxDynamicSharedMemorySize, SMEM_TOTAL);
        cudaFuncSetAttribute(pass1_kernel,
                             cudaFuncAttributeMaxDynamicSharedMemorySize, SMEM_TOTAL);
    }
    long long lossIdx = (long long)out_size - 1;

    convert_kernel<<<(N_ROWS * DIM / 4 + VOCAB * DIM / 4 + 255) / 256, 256>>>(inp, emb);
    for (int i = 0; i < NCH; i++) {
        pass0_kernel<<<GRID0, 256, SMEM_TOTAL>>>(i * CHUNK);
        cudaEventRecord(ev[i], 0);
        cudaStreamWaitEvent(sB, ev[i], 0);
        pass1_kernel<<<GRID1 + 2, 256, SMEM_TOTAL, sB>>>(i * CHUNK, out, label, inp, emb, lossIdx);
    }
    cudaEventRecord(evJoin, sB);
    cudaStreamWaitEvent(0, evJoin, 0);             // join: harness stream sees completion
}

// round 14
// speedup vs baseline: 1.2662x; 1.2662x over previous
#include <cuda_runtime.h>
#include <cuda_fp16.h>
#include <cstdint>

#define N_ROWS 4096
#define VOCAB  50000
#define DIM    64

#define BM 128
#define BN 128
#define TPB   391                 // column tiles per row-block
#define MB    32                  // row blocks
#define HALF  (16 * TPB)          // 6256 tiles per half
#define GRIDS 444                 // 3 CTAs/SM x 148 SMs

#define ROWB 144                  // bytes per smem tile row (72 halves, conflict-free)
#define TILE_SM (BM * ROWB)       // 18432
#define SMEM_PASS (3 * TILE_SM)   // A + B double buffer = 55296
#define SMEM_MIX  (4 * TILE_SM)   // As0 + As1 + B double buffer = 73728

#define LOG2E 1.4426950408889634f

// scratch (no allocs allowed -> device globals)
__device__ float  g_sums[N_ROWS];
__device__ float  g_loss;
__device__ int    g_loss_cnt;
__device__ __half g_A16[N_ROWS * DIM];   // pre-scaled by log2e
__device__ __half g_B16[VOCAB * DIM];

__device__ __forceinline__ uint32_t smem_u32(const void* p) {
    uint32_t a;
    asm("{ .reg .u64 t; cvta.to.shared.u64 t, %1; cvt.u32.u64 %0, t; }" : "=r"(a) : "l"(p));
    return a;
}
__device__ __forceinline__ float ex2f(float x) {      // exp(logit): logits log2-domain
    float y;
    asm("ex2.approx.f32 %0, %1;" : "=f"(y) : "f"(x));
    return y;
}
// B-tile column permutation: MMA-space row q = nf*8+lc*2+j holds natural column
// (nf&2)*8 + lc*4 + (nf&1)*2 + j  -> pass-1 stores are full STG.128.
__device__ __forceinline__ int permB(int r) {
    int q = r & 31;
    int nf = q >> 3, lc = (q >> 1) & 3, j = q & 1;
    return (r & ~31) | ((nf & 2) << 3) | (lc << 2) | ((nf & 1) << 1) | j;
}
#define CP_ASYNC16(dst, src, sz) \
    asm volatile("cp.async.cg.shared.global [%0], [%1], 16, %2;" :: "r"(dst), "l"(src), "r"(sz))
#define CP_COMMIT()  asm volatile("cp.async.commit_group;" ::: "memory")
#define CP_WAIT0()   asm volatile("cp.async.wait_group 0;" ::: "memory")
#define LDMATRIX_X4(r0, r1, r2, r3, addr) \
    asm volatile("ldmatrix.sync.aligned.m8n8.x4.shared.b16 {%0,%1,%2,%3}, [%4];" \
                 : "=r"(r0), "=r"(r1), "=r"(r2), "=r"(r3) : "r"(addr))

// init + fp32 -> fp16 convert. A pre-scaled by log2e so exp(logit) == ex2(gemm_out).
__global__ void convert_kernel(const float* __restrict__ A, const float* __restrict__ B) {
    int i = blockIdx.x * blockDim.x + threadIdx.x;
    if (i < N_ROWS) g_sums[i] = 0.f;
    if (i == 0) { g_loss = 0.f; g_loss_cnt = 0; }
    const int nA4 = N_ROWS * DIM / 4;
    const int nB4 = VOCAB * DIM / 4;
    if (i < nA4) {
        float4 v = ((const float4*)A)[i];
        __half2* d = (__half2*)g_A16;
        d[i * 2 + 0] = __floats2half2_rn(v.x * LOG2E, v.y * LOG2E);
        d[i * 2 + 1] = __floats2half2_rn(v.z * LOG2E, v.w * LOG2E);
    }
    int j = i - nA4;
    if (j >= 0 && j < nB4) {
        float4 v = ((const float4*)B)[j];
        __half2* d = (__half2*)g_B16;
        d[j * 2 + 0] = __floats2half2_rn(v.x, v.y);
        d[j * 2 + 1] = __floats2half2_rn(v.z, v.w);
    }
}

// ---- shared strip machinery (R10-proven) ----
struct StripCtx {
    uint32_t sA, sB0, aAddr0, bOff0;
    int tid, lane, mBase, nBase, lr, lc;
};
__device__ __forceinline__ void strip_init(StripCtx& S, char* smem, int nABufs) {
    S.sA = smem_u32(smem);
    S.sB0 = S.sA + nABufs * TILE_SM;
    S.tid = threadIdx.x;
    S.lane = S.tid & 31;
    int wid = S.tid >> 5;
    S.mBase = (wid >> 2) * 64; S.nBase = (wid & 3) * 32;
    S.lr = S.lane >> 2; S.lc = S.lane & 3;
    S.aAddr0 = S.sA +
        (uint32_t)(S.mBase + ((S.lane >> 3) & 1) * 8 + (S.lane & 7)) * ROWB + (S.lane >> 4) * 16;
    S.bOff0 =
        (uint32_t)(S.nBase + (S.lane >> 4) * 8 + (S.lane & 7)) * ROWB + ((S.lane >> 3) & 1) * 16;
}
__device__ __forceinline__ void prefetchB(const StripCtx& S, int v0, uint32_t dstBase) {
    #pragma unroll
    for (int t = 0; t < 4; t++) {
        int i = S.tid + t * 256;
        int row = i >> 3, c8 = i & 7;
        int v = v0 + permB(row);
        uint32_t dst = dstBase + row * ROWB + c8 * 16;
        const __half* src = g_B16 + (size_t)v * DIM + c8 * 8;
        CP_ASYNC16(dst, src, (v < VOCAB) ? 16 : 0);
    }
    CP_COMMIT();
}
__device__ __forceinline__ void loadA(const StripCtx& S, char* dst, int m0) {
    const uint4* Ag = (const uint4*)(g_A16 + (size_t)m0 * DIM);
    #pragma unroll
    for (int t = 0; t < 4; t++) {
        int i = S.tid + t * 256;
        int row = i >> 3, c8 = i & 7;
        *(uint4*)(dst + row * ROWB + c8 * 16) = Ag[i];
    }
}
__device__ __forceinline__ void flush_sums(const StripCtx& S, int m, float* racc) {
    #pragma unroll
    for (int k = 0; k < 8; k++) {
        float s = racc[k];
        s += __shfl_xor_sync(0xffffffffu, s, 1);
        s += __shfl_xor_sync(0xffffffffu, s, 2);
        if (S.lc == 0)
            atomicAdd(&g_sums[m * BM + S.mBase + (k >> 1) * 16 + (k & 1) * 8 + S.lr], s);
        racc[k] = 0.f;
    }
}
__device__ __forceinline__ void load_rinv(const StripCtx& S, int m, float* rinv) {
    #pragma unroll
    for (int k = 0; k < 8; k++)
        rinv[k] = 1.0f / __ldcg(&g_sums[m * BM + S.mBase + (k >> 1) * 16 + (k & 1) * 8 + S.lr]);
}
// One tile: preload B frags, mf-major slabs (16 MMA + slab epilogue).
template <bool P0>
__device__ __forceinline__ void run_tile(const StripCtx& S, uint32_t aAddr0,
                                         int v0, int m0, int buf,
                                         float* rr, float* __restrict__ out) {
    const uint32_t bAddr0 = S.sB0 + buf * TILE_SM + S.bOff0;
    unsigned bf[4][4][2];
    #pragma unroll
    for (int kk = 0; kk < 4; kk++)
        #pragma unroll
        for (int p = 0; p < 2; p++)
            LDMATRIX_X4(bf[kk][2 * p][0], bf[kk][2 * p][1],
                        bf[kk][2 * p + 1][0], bf[kk][2 * p + 1][1],
                        bAddr0 + p * (16 * ROWB) + kk * 32);
    const bool full = (v0 + BN <= VOCAB);
    #pragma unroll
    for (int mf = 0; mf < 4; mf++) {
        float c[4][4];
        #pragma unroll
        for (int nf = 0; nf < 4; nf++)
            #pragma unroll
            for (int d = 0; d < 4; d++) c[nf][d] = 0.f;
        #pragma unroll
        for (int kk = 0; kk < 4; kk++) {
            unsigned a0, a1, a2, a3;
            LDMATRIX_X4(a0, a1, a2, a3, aAddr0 + mf * (16 * ROWB) + kk * 32);
            #pragma unroll
            for (int nf = 0; nf < 4; nf++) {
                asm volatile(
                    "mma.sync.aligned.m16n8k16.row.col.f32.f16.f16.f32 "
                    "{%0,%1,%2,%3}, {%4,%5,%6,%7}, {%8,%9}, {%0,%1,%2,%3};"
                    : "+f"(c[nf][0]), "+f"(c[nf][1]), "+f"(c[nf][2]), "+f"(c[nf][3])
                    : "r"(a0), "r"(a1), "r"(a2), "r"(a3),
                      "r"(bf[kk][nf][0]), "r"(bf[kk][nf][1]));
            }
        }
        if (P0) {
            if (full) {
                #pragma unroll
                for (int h = 0; h < 2; h++) {
                    __half2 hs = __floats2half2_rn(0.f, 0.f);
                    #pragma unroll
                    for (int nf = 0; nf < 4; nf++) {
                        __half2 p = __floats2half2_rn(c[nf][h * 2 + 0], c[nf][h * 2 + 1]);
                        hs = __hadd2(hs, h2exp2(p));
                    }
                    float2 f = __half22float2(hs);
                    rr[mf * 2 + h] += f.x + f.y;
                }
            } else {
                #pragma unroll
                for (int h = 0; h < 2; h++) {
                    float s = 0.f;
                    #pragma unroll
                    for (int nf = 0; nf < 4; nf++) {
                        int col = v0 + S.nBase + (nf >> 1) * 16 + S.lc * 4 + (nf & 1) * 2;
                        float e0 = ex2f(c[nf][h * 2 + 0]);
                        float e1 = ex2f(c[nf][h * 2 + 1]);
                        s += (col     < VOCAB) ? e0 : 0.f;
                        s += (col + 1 < VOCAB) ? e1 : 0.f;
                    }
                    rr[mf * 2 + h] += s;
                }
            }
        } else {
            #pragma unroll
            for (int h = 0; h < 2; h++) {
                const float r = rr[mf * 2 + h];
                const int rl = S.mBase + mf * 16 + h * 8 + S.lr;
                float* op = out + (size_t)(m0 + rl) * VOCAB;
                #pragma unroll
                for (int gg = 0; gg < 2; gg++) {
                    int col = v0 + S.nBase + gg * 16 + S.lc * 4;
                    if (full || col < VOCAB) {   // 50000 % 4 == 0 -> no straddle
                        float4 p;
                        p.x = ex2f(c[2 * gg + 0][h * 2 + 0]) * r;
                        p.y = ex2f(c[2 * gg + 0][h * 2 + 1]) * r;
                        p.z = ex2f(c[2 * gg + 1][h * 2 + 0]) * r;
                        p.w = ex2f(c[2 * gg + 1][h * 2 + 1]) * r;
                        __stcs((float4*)(op + col), p);
                    }
                }
            }
        }
    }
}
// 256-row loss reduction (one CTA); final writer emits scalar. 16 CTAs total.
__device__ __forceinline__ void loss_block(int r0, const int* label_words,
                                           const float* inp, const float* emb,
                                           float* out, long long lossIdx, char* smem) {
    const int tid = threadIdx.x;
    bool is64 = true;                              // int64 labels: odd words all zero
    #pragma unroll
    for (int i = 0; i < 64; i++) is64 &= (label_words[2 * i + 1] == 0);
    int r = r0 + tid;
    int lab = is64 ? label_words[2 * r] : label_words[r];
    const float4* a4 = (const float4*)(inp + (size_t)r * DIM);
    const float4* b4 = (const float4*)(emb + (size_t)lab * DIM);
    float dot = 0.f;
    #pragma unroll
    for (int i = 0; i < DIM / 4; i++) {
        float4 x = a4[i], y = b4[i];
        dot += x.x * y.x + x.y * y.y + x.z * y.z + x.w * y.w;
    }
    float v = logf(__ldcg(&g_sums[r])) - dot;
    float* red = (float*)smem;
    red[tid] = v;
    __syncthreads();
    for (int s = 128; s > 0; s >>= 1) {
        if (tid < s) red[tid] += red[tid + s];
        __syncthreads();
    }
    if (tid == 0) {
        atomicAdd(&g_loss, red[0]);
        __threadfence();
        int c = atomicAdd(&g_loss_cnt, 1);
        if (c == 15)
            out[lossIdx] = atomicAdd(&g_loss, 0.f) * (1.0f / (float)N_ROWS);
    }
}

// K1: pass0 on blocks 0..15 (sums only).
__global__ void __launch_bounds__(256, 3)
pass0_kernel() {
    extern __shared__ char smem[];
    StripCtx S; strip_init(S, smem, 1);
    const int b = blockIdx.x;
    const int base = HALF / GRIDS, rem = HALF % GRIDS;   // 14, 40
    const int gBeg = b * base + (b < rem ? b : rem);
    const int gEnd = gBeg + base + (b < rem ? 1 : 0);

    prefetchB(S, (gBeg % TPB) * BN, S.sB0);
    int curM = -1, buf = 0;
    float rr[8];
    #pragma unroll
    for (int k = 0; k < 8; k++) rr[k] = 0.f;

    for (int g = gBeg; g < gEnd; g++) {
        const int m = g / TPB;
        const int v0 = (g % TPB) * BN;
        if (m != curM) {
            __syncthreads();
            if (curM >= 0) flush_sums(S, curM, rr);
            loadA(S, smem, m * BM);
            curM = m;
        }
        CP_WAIT0();
        __syncthreads();
        if (g + 1 < gEnd)
            prefetchB(S, ((g + 1) % TPB) * BN, S.sB0 + (buf ^ 1) * TILE_SM);
        run_tile<true>(S, S.aAddr0, v0, m * BM, buf, rr, nullptr);
        buf ^= 1;
    }
    if (curM >= 0) flush_sums(S, curM, rr);
}

// K2 (mix): alternate pass1 tiles of blocks 0..15 (sums final after K1) with
// pass0 tiles of blocks 16..31. Per-CTA alternation; zero inter-CTA sync.
// Loss CTAs (b >= GRIDS) reduce blocks 0..15.
__global__ void __launch_bounds__(256, 3)
mix_kernel(float* __restrict__ out,
           const int* __restrict__ label_words,
           const float* __restrict__ inp,
           const float* __restrict__ emb,
           long long lossIdx) {
    extern __shared__ char smem[];
    StripCtx S; strip_init(S, smem, 2);            // As0 | As1 | B0 | B1
    const int b = blockIdx.x;
    if (b >= GRIDS) {
        loss_block((b - GRIDS) * 256, label_words, inp, emb, out, lossIdx, smem);
        return;
    }
    const int base = HALF / GRIDS, rem = HALF % GRIDS;
    const int s0 = b * base + (b < rem ? b : rem);
    const int L = base + (b < rem ? 1 : 0);
    const int TSTEPS = 2 * L;

    // step t: even -> pass1 tile (blocks 0..15), odd -> pass0 tile (blocks 16..31)
    auto tile_of = [&](int t, bool& isP1, int& m, int& v0) {
        isP1 = !(t & 1);
        int g = s0 + (t >> 1);
        v0 = (g % TPB) * BN;
        m = (isP1 ? 0 : 16) + g / TPB;
    };

    { bool p; int m, v0; tile_of(0, p, m, v0); prefetchB(S, v0, S.sB0); }

    int buf = 0, curM0 = -1, curM1 = -1;
    float racc[8], rinv[8];
    #pragma unroll
    for (int k = 0; k < 8; k++) { racc[k] = 0.f; rinv[k] = 0.f; }

    for (int t = 0; t < TSTEPS; t++) {
        bool isP1; int m, v0;
        tile_of(t, isP1, m, v0);
        if (isP1) {
            if (m != curM1) {                      // safe: see barrier-chain argument
                loadA(S, smem + TILE_SM, m * BM);
                load_rinv(S, m, rinv);
                curM1 = m;
            }
        } else {
            if (m != curM0) {
                if (curM0 >= 0) flush_sums(S, curM0, racc);
                loadA(S, smem, m * BM);
                curM0 = m;
            }
        }
        CP_WAIT0();
        __syncthreads();
        if (t + 1 < TSTEPS) {
            bool p2; int m2, v2;
            tile_of(t + 1, p2, m2, v2);
            prefetchB(S, v2, S.sB0 + (buf ^ 1) * TILE_SM);
        }
        if (isP1) run_tile<false>(S, S.aAddr0 + TILE_SM, v0, m * BM, buf, rinv, out);
        else      run_tile<true>(S, S.aAddr0, v0, m * BM, buf, racc, nullptr);
        buf ^= 1;
    }
    if (curM0 >= 0) flush_sums(S, curM0, racc);
}

// K3: pass1 on blocks 16..31; loss CTAs reduce blocks 16..31.
__global__ void __launch_bounds__(256, 3)
pass1_kernel(float* __restrict__ out,
             const int* __restrict__ label_words,
             const float* __restrict__ inp,
             const float* __restrict__ emb,
             long long lossIdx) {
    extern __shared__ char smem[];
    StripCtx S; strip_init(S, smem, 1);
    const int b = blockIdx.x;
    if (b >= GRIDS) {
        loss_block(2048 + (b - GRIDS) * 256, label_words, inp, emb, out, lossIdx, smem);
        return;
    }
    const int base = HALF / GRIDS, rem = HALF % GRIDS;
    const int gBeg = b * base + (b < rem ? b : rem);
    const int gEnd = gBeg + base + (b < rem ? 1 : 0);

    prefetchB(S, (gBeg % TPB) * BN, S.sB0);
    int curM = -1, buf = 0;
    float rr[8];
    for (int g = gBeg; g < gEnd; g++) {
        const int m = 16 + g / TPB;
        const int v0 = (g % TPB) * BN;
        if (m != curM) {
            __syncthreads();
            loadA(S, smem, m * BM);
            load_rinv(S, m, rr);
            curM = m;
        }
        CP_WAIT0();
        __syncthreads();
        if (g + 1 < gEnd)
            prefetchB(S, ((g + 1) % TPB) * BN, S.sB0 + (buf ^ 1) * TILE_SM);
        run_tile<false>(S, S.aAddr0, v0, m * BM, buf, rr, out);
        buf ^= 1;
    }
}

extern "C" void kernel_launch(void* const* d_in, const int* in_sizes, int n_in,
                              void* d_out, int out_size) {
    const int*   label = (const int*)d_in[0];      // int32 or int64 (sniffed in-kernel)
    const float* inp   = (const float*)d_in[1];    // [4096, 64]
    const float* emb   = (const float*)d_in[2];    // [50000, 64]
    float* out = (float*)d_out;                    // [4096*50000] probs + [1] loss

    static int attr_done = 0;
    if (!attr_done) {
        cudaFuncSetAttribute(pass0_kernel,
                             cudaFuncAttributeMaxDynamicSharedMemorySize, SMEM_PASS);
        cudaFuncSetAttribute(mix_kernel,
                             cudaFuncAttributeMaxDynamicSharedMemorySize, SMEM_MIX);
        cudaFuncSetAttribute(pass1_kernel,
                             cudaFuncAttributeMaxDynamicSharedMemorySize, SMEM_PASS);
        attr_done = 1;
    }
    long long lossIdx = (long long)out_size - 1;

    convert_kernel<<<(N_ROWS * DIM / 4 + VOCAB * DIM / 4 + 255) / 256, 256>>>(inp, emb);
    pass0_kernel<<<GRIDS, 256, SMEM_PASS>>>();
    mix_kernel<<<GRIDS + 8, 256, SMEM_MIX>>>(out, label, inp, emb, lossIdx);
    pass1_kernel<<<GRIDS + 8, 256, SMEM_PASS>>>(out, label, inp, emb, lossIdx);
}